// round 5
// baseline (speedup 1.0000x reference)
#include <cuda_runtime.h>
#include <cuda_bf16.h>
#include <cstdint>

#define B4 4096
#define N2 8192
#define DZ 128
#define DF 2048
#define LCOLS 8191

// output layout (float32): loss[1], logits[8192*8191], labels[8192], lids_k32[8192], lids_k512[8192]
#define OUT_LOSS    0ull
#define OUT_LOGITS  1ull
#define OUT_LABELS  (1ull + (unsigned long long)N2 * LCOLS)
#define OUT_LIDS32  (OUT_LABELS + N2)
#define OUT_LIDS512 (OUT_LIDS32 + N2)

// scratch (device globals: allocation-free per harness rules)
__device__ __nv_bfloat16 g_fhi[(size_t)N2 * DF];
__device__ __nv_bfloat16 g_flo[(size_t)N2 * DF];
__device__ __nv_bfloat16 g_zhi[N2 * DZ];
__device__ __nv_bfloat16 g_zlo[N2 * DZ];
__device__ float g_fn[N2];
__device__ float g_D[(size_t)N2 * N2];     // 256 MiB
__device__ float g_lossper[N2];

// ---------------------------------------------------------------------------
// PTX helpers (plain sm_103-safe: mma.sync / ldmatrix / cp.async only)
// ---------------------------------------------------------------------------
__device__ __forceinline__ uint32_t smem_u32(const void* p) {
    uint32_t a;
    asm("{ .reg .u64 t; cvta.to.shared.u64 t, %1; cvt.u32.u64 %0, t; }" : "=r"(a) : "l"(p));
    return a;
}

#define CP_ASYNC16(dst, src) \
    asm volatile("cp.async.cg.shared.global [%0], [%1], 16;" :: "r"(dst), "l"(src) : "memory")
#define CP_COMMIT() asm volatile("cp.async.commit_group;" ::: "memory")
#define CP_WAIT1()  asm volatile("cp.async.wait_group 1;" ::: "memory")
#define CP_WAIT0()  asm volatile("cp.async.wait_group 0;" ::: "memory")

#define LDSM4(r, addr) \
    asm volatile("ldmatrix.sync.aligned.m8n8.x4.shared.b16 {%0,%1,%2,%3}, [%4];" \
        : "=r"((r)[0]), "=r"((r)[1]), "=r"((r)[2]), "=r"((r)[3]) : "r"(addr))

#define MMA16816(d, a, b0, b1) \
    asm volatile("mma.sync.aligned.m16n8k16.row.col.f32.bf16.bf16.f32 " \
        "{%0,%1,%2,%3}, {%4,%5,%6,%7}, {%8,%9}, {%0,%1,%2,%3};" \
        : "+f"((d)[0]), "+f"((d)[1]), "+f"((d)[2]), "+f"((d)[3]) \
        : "r"((a)[0]), "r"((a)[1]), "r"((a)[2]), "r"((a)[3]), "r"(b0), "r"(b1))

// off-diag column mapping (row gi, logical col gj) -> packed col, -1 = diag
__device__ __forceinline__ int colmap(int gi, int gj) {
    if (gi < B4) {
        if (gj >= B4) return gj - B4;
        if (gj == gi) return -1;
        return B4 + gj - (gj > gi ? 1 : 0);
    } else {
        if (gj < B4) return gj;
        if (gj == gi) return -1;
        return gj - (gj > gi ? 1 : 0);
    }
}

// ---------------------------------------------------------------------------
// prep: f squared norms + bf16 splits, z normalize + bf16 splits, labels
// ---------------------------------------------------------------------------
__global__ void __launch_bounds__(256) prep_kernel(
    const float* __restrict__ z0, const float* __restrict__ z1,
    const float* __restrict__ f0, const float* __restrict__ f1,
    float* __restrict__ out)
{
    int r = blockIdx.x;
    int tid = threadIdx.x;
    __shared__ float sred[256];

    const float* f = (r < B4) ? (f0 + (size_t)r * DF) : (f1 + (size_t)(r - B4) * DF);
    float s = 0.f;
    for (int j = tid; j < DF; j += 256) {
        float v = f[j]; s += v * v;
        __nv_bfloat16 h = __float2bfloat16(v);
        g_fhi[(size_t)r * DF + j] = h;
        g_flo[(size_t)r * DF + j] = __float2bfloat16(v - __bfloat162float(h));
    }
    sred[tid] = s; __syncthreads();
    for (int st = 128; st > 0; st >>= 1) { if (tid < st) sred[tid] += sred[tid + st]; __syncthreads(); }
    if (tid == 0) g_fn[r] = sred[0];
    __syncthreads();

    const float* z = (r < B4) ? (z0 + (size_t)r * DZ) : (z1 + (size_t)(r - B4) * DZ);
    float v = (tid < DZ) ? z[tid] : 0.f;
    sred[tid] = v * v; __syncthreads();
    for (int st = 128; st > 0; st >>= 1) { if (tid < st) sred[tid] += sred[tid + st]; __syncthreads(); }
    float inv = 1.f / fmaxf(sqrtf(sred[0]), 1e-12f);
    if (tid < DZ) {
        float zn = v * inv;
        __nv_bfloat16 h = __float2bfloat16(zn);
        g_zhi[(size_t)r * DZ + tid] = h;
        g_zlo[(size_t)r * DZ + tid] = __float2bfloat16(zn - __bfloat162float(h));
    }
    if (tid == 0) out[OUT_LABELS + r] = (float)(r & (B4 - 1));
}

// ===========================================================================
// logits GEMM (K=128): CTA 128x128, warp 32x64, 2-stage. Triangle bc>=br,
// mirror via stride-129 smem transpose, scatter into off-diag layout.
// ===========================================================================
#define LSTAGE 40960              // Ah 10240 | Al 10240 | Bh 10240 | Bl 10240
#define ROWB 80                   // 64B data + 16B pad (LDSM conflict-free)
#define LSMEM_DYN (2 * LSTAGE)

__device__ __forceinline__ void load_stage_l(
    uint32_t sb, const __nv_bfloat16* __restrict__ hi, const __nv_bfloat16* __restrict__ lo,
    int aBase, int bBase, int kt)
{
    int tid = threadIdx.x;
    #pragma unroll
    for (int p = 0; p < 2; p++) {
        int c = tid + p * 256;
        int row = c >> 2, ch = c & 3;
        size_t offA = (size_t)(aBase + row) * DZ + kt + ch * 8;
        size_t offB = (size_t)(bBase + row) * DZ + kt + ch * 8;
        uint32_t d = sb + row * ROWB + ch * 16;
        CP_ASYNC16(d,         hi + offA);
        CP_ASYNC16(d + 10240, lo + offA);
        CP_ASYNC16(d + 20480, hi + offB);
        CP_ASYNC16(d + 30720, lo + offB);
    }
}

__global__ void __launch_bounds__(256, 1) logits_gemm_kernel(float* __restrict__ out)
{
    const int bc = blockIdx.x, br = blockIdx.y;
    if (bc < br) return;

    extern __shared__ char smem[];
    uint32_t sb = smem_u32(smem);
    const int tid = threadIdx.x, wid = tid >> 5, lane = tid & 31;
    const int aBase = br * 128, bBase = bc * 128;
    const int warpM = (wid & 3) * 32, warpN = (wid >> 2) * 64;

    const __nv_bfloat16* hi = &g_zhi[0];
    const __nv_bfloat16* lo = &g_zlo[0];

    float acc[2][8][4];
    #pragma unroll
    for (int m = 0; m < 2; m++)
        #pragma unroll
        for (int j = 0; j < 8; j++)
            #pragma unroll
            for (int q = 0; q < 4; q++) acc[m][j][q] = 0.f;

    const int aRow = lane & 15, aChunk = (lane >> 4) & 1;
    const int bRow = (lane & 7) | ((lane & 16) >> 1);
    const int bChunk = (lane >> 3) & 1;

    load_stage_l(sb, hi, lo, aBase, bBase, 0);
    CP_COMMIT();

    const int NK = DZ / 32;
    for (int it = 0; it < NK; it++) {
        const int s = it & 1;
        if (it + 1 < NK) {
            load_stage_l(sb + (s ^ 1) * LSTAGE, hi, lo, aBase, bBase, (it + 1) * 32);
            CP_COMMIT();
            CP_WAIT1();
        } else {
            CP_WAIT0();
        }
        __syncthreads();

        const uint32_t Ab = sb + s * LSTAGE;
        const uint32_t Bb = Ab + 20480;
        #pragma unroll
        for (int ks = 0; ks < 2; ks++) {
            uint32_t ah[2][4], al[2][4], bh[4][4], bl[4][4];
            uint32_t aAddr = Ab + (warpM + aRow) * ROWB + ks * 32 + aChunk * 16;
            LDSM4(ah[0], aAddr);
            LDSM4(ah[1], aAddr + 16 * ROWB);
            LDSM4(al[0], aAddr + 10240);
            LDSM4(al[1], aAddr + 10240 + 16 * ROWB);
            uint32_t bAddr = Bb + (warpN + bRow) * ROWB + ks * 32 + bChunk * 16;
            #pragma unroll
            for (int nt = 0; nt < 4; nt++) {
                LDSM4(bh[nt], bAddr + nt * 16 * ROWB);
                LDSM4(bl[nt], bAddr + 10240 + nt * 16 * ROWB);
            }
            #pragma unroll
            for (int mt = 0; mt < 2; mt++)
                #pragma unroll
                for (int j = 0; j < 8; j++) {
                    const int nt = j >> 1, hf = (j & 1) * 2;
                    MMA16816(acc[mt][j], ah[mt], bh[nt][hf], bh[nt][hf + 1]);
                    MMA16816(acc[mt][j], ah[mt], bl[nt][hf], bl[nt][hf + 1]);
                    MMA16816(acc[mt][j], al[mt], bh[nt][hf], bh[nt][hf + 1]);
                }
        }
        __syncthreads();
    }

    float* st = (float*)smem;
    #pragma unroll
    for (int mt = 0; mt < 2; mt++) {
        const int r0 = warpM + mt * 16 + (lane >> 2);
        #pragma unroll
        for (int j = 0; j < 8; j++) {
            const int c0 = warpN + (j >> 1) * 16 + (j & 1) * 8 + 2 * (lane & 3);
            #pragma unroll
            for (int q = 0; q < 4; q++)
                st[(r0 + (q >> 1) * 8) * 129 + c0 + (q & 1)] = 2.f * acc[mt][j][q];
        }
    }
    __syncthreads();

    for (int x = tid; x < 128 * 128; x += 256) {
        int mm = x >> 7, cc = x & 127;
        int col = colmap(aBase + mm, bBase + cc);
        if (col >= 0) out[OUT_LOGITS + (size_t)(aBase + mm) * LCOLS + col] = st[mm * 129 + cc];
    }
    if (bc > br) {
        for (int x = tid; x < 128 * 128; x += 256) {
            int rc = x >> 7, cm = x & 127;
            int col = colmap(bBase + rc, aBase + cm);
            if (col >= 0) out[OUT_LOGITS + (size_t)(bBase + rc) * LCOLS + col] = st[cm * 129 + rc];
        }
    }
}

// ===========================================================================
// dist GEMM (K=2048): CTA 256x128, 512 threads / 16 warps, warp 64x32
// (4M x 4N), BK=32, 3-stage cp.async ring, prefetch-early, one sync per iter.
// Tiles bc >= 2*br; mirror writes guarded gj > gi. d2 = max(ni+nj-2dot, 0).
// ===========================================================================
#define DSTG 61440                // AH 20480 | AL 20480 | BH 10240 | BL 10240
#define D_AL 20480
#define D_BH 40960
#define D_BL 51200
#define DSMEM_DYN (3 * DSTG)      // 184320 B

__device__ __forceinline__ void load_stage_d(
    uint32_t sb, int aBase, int bBase, int kt)
{
    int tid = threadIdx.x;
    // A: 256 rows x 4 chunks (hi & lo)
    #pragma unroll
    for (int p = 0; p < 2; p++) {
        int c = tid + p * 512;
        int row = c >> 2, ch = c & 3;
        size_t off = (size_t)(aBase + row) * DF + kt + ch * 8;
        uint32_t d = sb + row * ROWB + ch * 16;
        CP_ASYNC16(d,        g_fhi + off);
        CP_ASYNC16(d + D_AL, g_flo + off);
    }
    // B: 128 rows x 4 chunks (hi & lo)
    {
        int row = tid >> 2, ch = tid & 3;
        size_t off = (size_t)(bBase + row) * DF + kt + ch * 8;
        uint32_t d = sb + D_BH + row * ROWB + ch * 16;
        CP_ASYNC16(d,                 g_fhi + off);
        CP_ASYNC16(d + (D_BL - D_BH), g_flo + off);
    }
}

__global__ void __launch_bounds__(512, 1) dist_gemm_kernel()
{
    const int bc = blockIdx.x, br = blockIdx.y;
    if (bc < 2 * br) return;

    extern __shared__ char smem[];
    uint32_t sb = smem_u32(smem);
    const int tid = threadIdx.x, wid = tid >> 5, lane = tid & 31;
    const int aBase = br * 256, bBase = bc * 128;
    const int warpM = (wid & 3) * 64, warpN = (wid >> 2) * 32;

    float acc[4][4][4];
    #pragma unroll
    for (int m = 0; m < 4; m++)
        #pragma unroll
        for (int j = 0; j < 4; j++)
            #pragma unroll
            for (int q = 0; q < 4; q++) acc[m][j][q] = 0.f;

    const int aRow = lane & 15, aChunk = (lane >> 4) & 1;
    const int bRow = (lane & 7) | ((lane & 16) >> 1);
    const int bChunk = (lane >> 3) & 1;

    load_stage_d(sb, aBase, bBase, 0);
    CP_COMMIT();
    load_stage_d(sb + DSTG, aBase, bBase, 32);
    CP_COMMIT();

    const int NK = DF / 32;
    for (int it = 0; it < NK; it++) {
        CP_WAIT1();
        __syncthreads();
        if (it + 2 < NK) {
            load_stage_d(sb + ((it + 2) % 3) * DSTG, aBase, bBase, (it + 2) * 32);
            CP_COMMIT();
        }

        const uint32_t Ab = sb + (it % 3) * DSTG;
        const uint32_t Bb = Ab + D_BH;
        #pragma unroll
        for (int ks = 0; ks < 2; ks++) {
            uint32_t bh[2][4], bl[2][4];
            uint32_t bAddr = Bb + (warpN + bRow) * ROWB + ks * 32 + bChunk * 16;
            LDSM4(bh[0], bAddr);
            LDSM4(bh[1], bAddr + 16 * ROWB);
            LDSM4(bl[0], bAddr + (D_BL - D_BH));
            LDSM4(bl[1], bAddr + (D_BL - D_BH) + 16 * ROWB);
            uint32_t aAddr = Ab + (warpM + aRow) * ROWB + ks * 32 + aChunk * 16;
            #pragma unroll
            for (int mt = 0; mt < 4; mt++) {
                uint32_t ah[4], al[4];
                LDSM4(ah, aAddr + mt * 16 * ROWB);
                LDSM4(al, aAddr + D_AL + mt * 16 * ROWB);
                #pragma unroll
                for (int j = 0; j < 4; j++) {
                    const int nt = j >> 1, hf = (j & 1) * 2;
                    MMA16816(acc[mt][j], ah, bh[nt][hf], bh[nt][hf + 1]);
                    MMA16816(acc[mt][j], ah, bl[nt][hf], bl[nt][hf + 1]);
                    MMA16816(acc[mt][j], al, bh[nt][hf], bh[nt][hf + 1]);
                }
            }
        }
    }

    // ---- epilogue ----
    __shared__ float sNi[256], sNj[128];
    if (tid < 256) sNi[tid] = g_fn[aBase + tid];
    else if (tid < 384) sNj[tid - 256] = g_fn[bBase + tid - 256];
    __syncthreads();

    float* st = (float*)smem;   // [256][129]
    #pragma unroll
    for (int mt = 0; mt < 4; mt++) {
        const int r0 = warpM + mt * 16 + (lane >> 2);
        #pragma unroll
        for (int j = 0; j < 4; j++) {
            const int c0 = warpN + (j >> 1) * 16 + (j & 1) * 8 + 2 * (lane & 3);
            #pragma unroll
            for (int q = 0; q < 4; q++) {
                const int rr = r0 + (q >> 1) * 8;
                const int cc = c0 + (q & 1);
                st[rr * 129 + cc] = fmaxf(sNi[rr] + sNj[cc] - 2.f * acc[mt][j][q], 0.f);
            }
        }
    }
    __syncthreads();

    for (int x = tid; x < 256 * 128; x += 512) {
        int mm = x >> 7, cc = x & 127;
        g_D[(size_t)(aBase + mm) * N2 + (bBase + cc)] = st[mm * 129 + cc];
    }
    for (int x = tid; x < 128 * 256; x += 512) {
        int rc = x >> 8, cm = x & 255;
        int gi = aBase + cm, gj = bBase + rc;
        if (gj > gi) g_D[(size_t)gj * N2 + gi] = st[cm * 129 + rc];
    }
}

// ---------------------------------------------------------------------------
// loss: per-row online logsumexp over the 8191 logits, minus positive logit
// ---------------------------------------------------------------------------
__global__ void __launch_bounds__(256) loss_kernel(const float* __restrict__ out)
{
    int r = blockIdx.x, tid = threadIdx.x;
    const float* row = out + OUT_LOGITS + (size_t)r * LCOLS;
    float m = -1e30f, s = 0.f;
    for (int j = tid; j < LCOLS; j += 256) {
        float v = row[j];
        if (v > m) { s = s * __expf(m - v) + 1.f; m = v; }
        else       { s += __expf(v - m); }
    }
    __shared__ float sm[256], ss[256];
    sm[tid] = m; ss[tid] = s; __syncthreads();
    for (int st = 128; st > 0; st >>= 1) {
        if (tid < st) {
            float m1 = sm[tid], s1 = ss[tid];
            float m2 = sm[tid + st], s2 = ss[tid + st];
            float M = fmaxf(m1, m2);
            ss[tid] = s1 * __expf(m1 - M) + s2 * __expf(m2 - M);
            sm[tid] = M;
        }
        __syncthreads();
    }
    if (tid == 0)
        g_lossper[r] = (sm[0] + logf(ss[0])) - row[r & (B4 - 1)];
}

__global__ void __launch_bounds__(256) finalize_kernel(float* __restrict__ out)
{
    __shared__ double sred[256];
    int tid = threadIdx.x;
    double s = 0.0;
    for (int j = tid; j < N2; j += 256) s += (double)g_lossper[j];
    sred[tid] = s; __syncthreads();
    for (int st = 128; st > 0; st >>= 1) { if (tid < st) sred[tid] += sred[tid + st]; __syncthreads(); }
    if (tid == 0) out[OUT_LOSS] = (float)(sred[0] / (double)N2);
}

// ---------------------------------------------------------------------------
// LID: per row, exact radix-select of rank-32 / rank-512 squared distance
// ---------------------------------------------------------------------------
__global__ void __launch_bounds__(256) select_kernel(float* __restrict__ out)
{
    int r = blockIdx.x, tid = threadIdx.x;
    __shared__ unsigned skey[N2];
    __shared__ unsigned hist[256];
    __shared__ unsigned s_prefix;
    __shared__ int s_kk;
    __shared__ float sred[256];

    const float* drow = &g_D[(size_t)r * N2];
    for (int j = tid; j < N2; j += 256)
        skey[j] = (j == r) ? 0xFFFFFFFFu : __float_as_uint(drow[j]);
    __syncthreads();

    #pragma unroll
    for (int ksel = 0; ksel < 2; ksel++) {
        const int k = (ksel == 0) ? 32 : 512;
        if (tid == 0) { s_kk = k; s_prefix = 0u; }
        __syncthreads();
        unsigned prefix = 0u, pmask = 0u;

        for (int p = 3; p >= 0; p--) {
            hist[tid] = 0u;
            __syncthreads();
            const int sh = p * 8;
            for (int j = tid; j < N2; j += 256) {
                unsigned kv = skey[j];
                unsigned bin = 0xFFFFFFFFu;
                if ((kv & pmask) == prefix) bin = (kv >> sh) & 255u;
                unsigned mm = __match_any_sync(0xFFFFFFFFu, bin);
                if (bin != 0xFFFFFFFFu && (int)(__ffs(mm) - 1) == (int)(threadIdx.x & 31))
                    atomicAdd(&hist[bin], (unsigned)__popc(mm));
            }
            __syncthreads();
            if (tid == 0) {
                int kk = s_kk, cum = 0;
                for (int b2 = 0; b2 < 256; b2++) {
                    int c = (int)hist[b2];
                    if (cum + c >= kk) { s_prefix = prefix | ((unsigned)b2 << sh); s_kk = kk - cum; break; }
                    cum += c;
                }
            }
            __syncthreads();
            prefix = s_prefix;
            pmask |= (0xFFu << sh);
        }

        const unsigned Kk = prefix;
        const float lnK = 0.5f * logf(__uint_as_float(Kk));
        float s = 0.f;
        for (int j = tid; j < N2; j += 256) {
            unsigned kv = skey[j];
            if (kv < Kk) s += 0.5f * logf(__uint_as_float(kv)) - lnK;
        }
        sred[tid] = s; __syncthreads();
        for (int st = 128; st > 0; st >>= 1) { if (tid < st) sred[tid] += sred[tid + st]; __syncthreads(); }
        if (tid == 0)
            out[(ksel == 0 ? OUT_LIDS32 : OUT_LIDS512) + r] = -(float)k / sred[0];
        __syncthreads();
    }
}

// ---------------------------------------------------------------------------
extern "C" void kernel_launch(void* const* d_in, const int* in_sizes, int n_in,
                              void* d_out, int out_size)
{
    const float* z0 = (const float*)d_in[0];
    const float* z1 = (const float*)d_in[1];
    const float* f0 = (const float*)d_in[2];
    const float* f1 = (const float*)d_in[3];
    float* out = (float*)d_out;

    cudaFuncSetAttribute(dist_gemm_kernel,
                         cudaFuncAttributeMaxDynamicSharedMemorySize, DSMEM_DYN);
    cudaFuncSetAttribute(logits_gemm_kernel,
                         cudaFuncAttributeMaxDynamicSharedMemorySize, LSMEM_DYN);

    // order chosen so ncu's fixed capture slot (4th kernel) lands on dist_gemm
    prep_kernel<<<N2, 256>>>(z0, z1, f0, f1, out);
    logits_gemm_kernel<<<dim3(64, 64), 256, LSMEM_DYN>>>(out);
    loss_kernel<<<N2, 256>>>(out);
    dist_gemm_kernel<<<dim3(64, 32), 512, DSMEM_DYN>>>();
    finalize_kernel<<<1, 256>>>(out);
    select_kernel<<<N2, 256>>>(out);
}

// round 6
// speedup vs baseline: 1.0261x; 1.0261x over previous
#include <cuda_runtime.h>
#include <cuda_bf16.h>
#include <cstdint>

#define B4 4096
#define N2 8192
#define DZ 128
#define DF 2048
#define LCOLS 8191

// output layout (float32): loss[1], logits[8192*8191], labels[8192], lids_k32[8192], lids_k512[8192]
#define OUT_LOSS    0ull
#define OUT_LOGITS  1ull
#define OUT_LABELS  (1ull + (unsigned long long)N2 * LCOLS)
#define OUT_LIDS32  (OUT_LABELS + N2)
#define OUT_LIDS512 (OUT_LIDS32 + N2)

// scratch (device globals: allocation-free per harness rules)
__device__ __nv_bfloat16 g_fhi[(size_t)N2 * DF];
__device__ __nv_bfloat16 g_flo[(size_t)N2 * DF];
__device__ __nv_bfloat16 g_zhi[N2 * DZ];
__device__ __nv_bfloat16 g_zlo[N2 * DZ];
__device__ float g_fn[N2];
__device__ float g_D[(size_t)N2 * N2];     // 256 MiB
__device__ float g_ls[64 * N2];            // per-(tile-slot,row) exp partial sums
__device__ float g_lossper[N2];

// ---------------------------------------------------------------------------
// PTX helpers (plain sm_103-safe: mma.sync / ldmatrix / cp.async only)
// ---------------------------------------------------------------------------
__device__ __forceinline__ uint32_t smem_u32(const void* p) {
    uint32_t a;
    asm("{ .reg .u64 t; cvta.to.shared.u64 t, %1; cvt.u32.u64 %0, t; }" : "=r"(a) : "l"(p));
    return a;
}

#define CP_ASYNC16(dst, src) \
    asm volatile("cp.async.cg.shared.global [%0], [%1], 16;" :: "r"(dst), "l"(src) : "memory")
#define CP_COMMIT() asm volatile("cp.async.commit_group;" ::: "memory")
#define CP_WAIT1()  asm volatile("cp.async.wait_group 1;" ::: "memory")
#define CP_WAIT0()  asm volatile("cp.async.wait_group 0;" ::: "memory")

#define LDSM4(r, addr) \
    asm volatile("ldmatrix.sync.aligned.m8n8.x4.shared.b16 {%0,%1,%2,%3}, [%4];" \
        : "=r"((r)[0]), "=r"((r)[1]), "=r"((r)[2]), "=r"((r)[3]) : "r"(addr))

#define MMA16816(d, a, b0, b1) \
    asm volatile("mma.sync.aligned.m16n8k16.row.col.f32.bf16.bf16.f32 " \
        "{%0,%1,%2,%3}, {%4,%5,%6,%7}, {%8,%9}, {%0,%1,%2,%3};" \
        : "+f"((d)[0]), "+f"((d)[1]), "+f"((d)[2]), "+f"((d)[3]) \
        : "r"((a)[0]), "r"((a)[1]), "r"((a)[2]), "r"((a)[3]), "r"(b0), "r"(b1))

// off-diag column mapping (row gi, logical col gj) -> packed col, -1 = diag
__device__ __forceinline__ int colmap(int gi, int gj) {
    if (gi < B4) {
        if (gj >= B4) return gj - B4;
        if (gj == gi) return -1;
        return B4 + gj - (gj > gi ? 1 : 0);
    } else {
        if (gj < B4) return gj;
        if (gj == gi) return -1;
        return gj - (gj > gi ? 1 : 0);
    }
}

// ---------------------------------------------------------------------------
// prep: f squared norms + bf16 splits, z normalize + bf16 splits, labels
// ---------------------------------------------------------------------------
__global__ void __launch_bounds__(256) prep_kernel(
    const float* __restrict__ z0, const float* __restrict__ z1,
    const float* __restrict__ f0, const float* __restrict__ f1,
    float* __restrict__ out)
{
    int r = blockIdx.x;
    int tid = threadIdx.x;
    __shared__ float sred[256];

    const float* f = (r < B4) ? (f0 + (size_t)r * DF) : (f1 + (size_t)(r - B4) * DF);
    float s = 0.f;
    for (int j = tid; j < DF; j += 256) {
        float v = f[j]; s += v * v;
        __nv_bfloat16 h = __float2bfloat16(v);
        g_fhi[(size_t)r * DF + j] = h;
        g_flo[(size_t)r * DF + j] = __float2bfloat16(v - __bfloat162float(h));
    }
    sred[tid] = s; __syncthreads();
    for (int st = 128; st > 0; st >>= 1) { if (tid < st) sred[tid] += sred[tid + st]; __syncthreads(); }
    if (tid == 0) g_fn[r] = sred[0];
    __syncthreads();

    const float* z = (r < B4) ? (z0 + (size_t)r * DZ) : (z1 + (size_t)(r - B4) * DZ);
    float v = (tid < DZ) ? z[tid] : 0.f;
    sred[tid] = v * v; __syncthreads();
    for (int st = 128; st > 0; st >>= 1) { if (tid < st) sred[tid] += sred[tid + st]; __syncthreads(); }
    float inv = 1.f / fmaxf(sqrtf(sred[0]), 1e-12f);
    if (tid < DZ) {
        float zn = v * inv;
        __nv_bfloat16 h = __float2bfloat16(zn);
        g_zhi[(size_t)r * DZ + tid] = h;
        g_zlo[(size_t)r * DZ + tid] = __float2bfloat16(zn - __bfloat162float(h));
    }
    if (tid == 0) out[OUT_LABELS + r] = (float)(r & (B4 - 1));
}

// ===========================================================================
// logits GEMM (K=128): CTA 128x128, warp 32x64, 2-stage. Triangle bc>=br,
// mirror via stride-129 smem transpose, scatter into off-diag layout.
// Fused softmax-denominator partials: exp tile once (symmetry halves exps),
// row sums -> g_ls[bc][aRow], col sums -> g_ls[br][bCol]. No atomics.
// ===========================================================================
#define LSTAGE 40960              // Ah 10240 | Al 10240 | Bh 10240 | Bl 10240
#define ROWB 80                   // 64B data + 16B pad (LDSM conflict-free)
#define LSMEM_DYN (2 * LSTAGE)

__device__ __forceinline__ void load_stage_l(
    uint32_t sb, const __nv_bfloat16* __restrict__ hi, const __nv_bfloat16* __restrict__ lo,
    int aBase, int bBase, int kt)
{
    int tid = threadIdx.x;
    #pragma unroll
    for (int p = 0; p < 2; p++) {
        int c = tid + p * 256;
        int row = c >> 2, ch = c & 3;
        size_t offA = (size_t)(aBase + row) * DZ + kt + ch * 8;
        size_t offB = (size_t)(bBase + row) * DZ + kt + ch * 8;
        uint32_t d = sb + row * ROWB + ch * 16;
        CP_ASYNC16(d,         hi + offA);
        CP_ASYNC16(d + 10240, lo + offA);
        CP_ASYNC16(d + 20480, hi + offB);
        CP_ASYNC16(d + 30720, lo + offB);
    }
}

__global__ void __launch_bounds__(256, 1) logits_gemm_kernel(float* __restrict__ out)
{
    const int bc = blockIdx.x, br = blockIdx.y;
    if (bc < br) return;

    extern __shared__ char smem[];
    uint32_t sb = smem_u32(smem);
    const int tid = threadIdx.x, wid = tid >> 5, lane = tid & 31;
    const int aBase = br * 128, bBase = bc * 128;
    const int warpM = (wid & 3) * 32, warpN = (wid >> 2) * 64;

    const __nv_bfloat16* hi = &g_zhi[0];
    const __nv_bfloat16* lo = &g_zlo[0];

    float acc[2][8][4];
    #pragma unroll
    for (int m = 0; m < 2; m++)
        #pragma unroll
        for (int j = 0; j < 8; j++)
            #pragma unroll
            for (int q = 0; q < 4; q++) acc[m][j][q] = 0.f;

    const int aRow = lane & 15, aChunk = (lane >> 4) & 1;
    const int bRow = (lane & 7) | ((lane & 16) >> 1);
    const int bChunk = (lane >> 3) & 1;

    load_stage_l(sb, hi, lo, aBase, bBase, 0);
    CP_COMMIT();

    const int NK = DZ / 32;
    for (int it = 0; it < NK; it++) {
        const int s = it & 1;
        if (it + 1 < NK) {
            load_stage_l(sb + (s ^ 1) * LSTAGE, hi, lo, aBase, bBase, (it + 1) * 32);
            CP_COMMIT();
            CP_WAIT1();
        } else {
            CP_WAIT0();
        }
        __syncthreads();

        const uint32_t Ab = sb + s * LSTAGE;
        const uint32_t Bb = Ab + 20480;
        #pragma unroll
        for (int ks = 0; ks < 2; ks++) {
            uint32_t ah[2][4], al[2][4], bh[4][4], bl[4][4];
            uint32_t aAddr = Ab + (warpM + aRow) * ROWB + ks * 32 + aChunk * 16;
            LDSM4(ah[0], aAddr);
            LDSM4(ah[1], aAddr + 16 * ROWB);
            LDSM4(al[0], aAddr + 10240);
            LDSM4(al[1], aAddr + 10240 + 16 * ROWB);
            uint32_t bAddr = Bb + (warpN + bRow) * ROWB + ks * 32 + bChunk * 16;
            #pragma unroll
            for (int nt = 0; nt < 4; nt++) {
                LDSM4(bh[nt], bAddr + nt * 16 * ROWB);
                LDSM4(bl[nt], bAddr + 10240 + nt * 16 * ROWB);
            }
            #pragma unroll
            for (int mt = 0; mt < 2; mt++)
                #pragma unroll
                for (int j = 0; j < 8; j++) {
                    const int nt = j >> 1, hf = (j & 1) * 2;
                    MMA16816(acc[mt][j], ah[mt], bh[nt][hf], bh[nt][hf + 1]);
                    MMA16816(acc[mt][j], ah[mt], bl[nt][hf], bl[nt][hf + 1]);
                    MMA16816(acc[mt][j], al[mt], bh[nt][hf], bh[nt][hf + 1]);
                }
        }
        __syncthreads();
    }

    float* st = (float*)smem;
    #pragma unroll
    for (int mt = 0; mt < 2; mt++) {
        const int r0 = warpM + mt * 16 + (lane >> 2);
        #pragma unroll
        for (int j = 0; j < 8; j++) {
            const int c0 = warpN + (j >> 1) * 16 + (j & 1) * 8 + 2 * (lane & 3);
            #pragma unroll
            for (int q = 0; q < 4; q++)
                st[(r0 + (q >> 1) * 8) * 129 + c0 + (q & 1)] = 2.f * acc[mt][j][q];
        }
    }
    __syncthreads();

    for (int x = tid; x < 128 * 128; x += 256) {
        int mm = x >> 7, cc = x & 127;
        int col = colmap(aBase + mm, bBase + cc);
        if (col >= 0) out[OUT_LOGITS + (size_t)(aBase + mm) * LCOLS + col] = st[mm * 129 + cc];
    }
    if (bc > br) {
        for (int x = tid; x < 128 * 128; x += 256) {
            int rc = x >> 7, cm = x & 127;
            int col = colmap(bBase + rc, aBase + cm);
            if (col >= 0) out[OUT_LOGITS + (size_t)(bBase + rc) * LCOLS + col] = st[cm * 129 + rc];
        }
    }
    __syncthreads();

    // ---- fused exp + row/col partial sums (symmetry: triangle tiles only) ----
    for (int x = tid; x < 128 * 128; x += 256) {
        int mm = x >> 7, cc = x & 127;
        float e = __expf(st[mm * 129 + cc]);
        if (br == bc && mm == cc) e = 0.f;     // exclude diagonal
        st[mm * 129 + cc] = e;
    }
    __syncthreads();

    {   // row sums -> slot bc, rows aBase..aBase+127 (2 threads per row)
        int row = tid >> 1, half = tid & 1;
        float s = 0.f;
        #pragma unroll 4
        for (int c2 = half * 64; c2 < half * 64 + 64; c2++) s += st[row * 129 + c2];
        s += __shfl_xor_sync(0xFFFFFFFFu, s, 1);
        if (half == 0) g_ls[(size_t)bc * N2 + aBase + row] = s;
    }
    if (bc > br) {   // col sums -> slot br, rows bBase..bBase+127
        int col = tid >> 1, half = tid & 1;
        float s = 0.f;
        #pragma unroll 4
        for (int r2 = half * 64; r2 < half * 64 + 64; r2++) s += st[r2 * 129 + col];
        s += __shfl_xor_sync(0xFFFFFFFFu, s, 1);
        if (half == 0) g_ls[(size_t)br * N2 + bBase + col] = s;
    }
}

// ---------------------------------------------------------------------------
// loss_final: per row, S = sum of 64 partials; pos = 2*dot(z0n, z1n);
// loss = log(S) - pos   (logits in [-2,2] -> no max-shift needed)
// ---------------------------------------------------------------------------
__global__ void __launch_bounds__(128) loss_final_kernel()
{
    int r = blockIdx.x, tid = threadIdx.x;
    int pr = (r < B4) ? r + B4 : r - B4;

    float a = (float)g_zhi[(size_t)r * DZ + tid] + (float)g_zlo[(size_t)r * DZ + tid];
    float b = (float)g_zhi[(size_t)pr * DZ + tid] + (float)g_zlo[(size_t)pr * DZ + tid];
    float p = a * b;
    float S = (tid < 64) ? g_ls[(size_t)tid * N2 + r] : 0.f;

    #pragma unroll
    for (int d = 16; d > 0; d >>= 1) {
        p += __shfl_xor_sync(0xFFFFFFFFu, p, d);
        S += __shfl_xor_sync(0xFFFFFFFFu, S, d);
    }
    __shared__ float sp[4], sS[4];
    if ((tid & 31) == 0) { sp[tid >> 5] = p; sS[tid >> 5] = S; }
    __syncthreads();
    if (tid == 0) {
        float P = sp[0] + sp[1] + sp[2] + sp[3];
        float SS = sS[0] + sS[1] + sS[2] + sS[3];
        g_lossper[r] = logf(SS) - 2.f * P;
    }
}

__global__ void __launch_bounds__(256) finalize_kernel(float* __restrict__ out)
{
    __shared__ double sred[256];
    int tid = threadIdx.x;
    double s = 0.0;
    for (int j = tid; j < N2; j += 256) s += (double)g_lossper[j];
    sred[tid] = s; __syncthreads();
    for (int st = 128; st > 0; st >>= 1) { if (tid < st) sred[tid] += sred[tid + st]; __syncthreads(); }
    if (tid == 0) out[OUT_LOSS] = (float)(sred[0] / (double)N2);
}

// ===========================================================================
// dist GEMM (K=2048): CTA 256x128, warp 64x64 (8 warps: 4M x 2N), BK=32,
// 3-stage cp.async ring, one syncthreads per K-iter. Tiles bc >= 2*br;
// mirror writes guarded gj > gi. d2 = max(ni+nj-2dot, 0) -> g_D.
// ===========================================================================
#define DSTG 61440                // AH 20480 | AL 20480 | BH 10240 | BL 10240
#define D_AL 20480
#define D_BH 40960
#define D_BL 51200
#define DSMEM_DYN (3 * DSTG)      // 184320 B

__device__ __forceinline__ void load_stage_d(
    uint32_t sb, int aBase, int bBase, int kt)
{
    int tid = threadIdx.x;
    // A: 256 rows x 4 chunks (hi & lo)
    #pragma unroll
    for (int p = 0; p < 4; p++) {
        int c = tid + p * 256;
        int row = c >> 2, ch = c & 3;
        size_t off = (size_t)(aBase + row) * DF + kt + ch * 8;
        uint32_t d = sb + row * ROWB + ch * 16;
        CP_ASYNC16(d,        g_fhi + off);
        CP_ASYNC16(d + D_AL, g_flo + off);
    }
    // B: 128 rows x 4 chunks (hi & lo)
    #pragma unroll
    for (int p = 0; p < 2; p++) {
        int c = tid + p * 256;
        int row = c >> 2, ch = c & 3;
        size_t off = (size_t)(bBase + row) * DF + kt + ch * 8;
        uint32_t d = sb + D_BH + row * ROWB + ch * 16;
        CP_ASYNC16(d,                 g_fhi + off);
        CP_ASYNC16(d + (D_BL - D_BH), g_flo + off);
    }
}

__global__ void __launch_bounds__(256, 1) dist_gemm_kernel()
{
    const int bc = blockIdx.x, br = blockIdx.y;
    if (bc < 2 * br) return;

    extern __shared__ char smem[];
    uint32_t sb = smem_u32(smem);
    const int tid = threadIdx.x, wid = tid >> 5, lane = tid & 31;
    const int aBase = br * 256, bBase = bc * 128;
    const int warpM = (wid & 3) * 64, warpN = (wid >> 2) * 64;

    float acc[4][8][4];
    #pragma unroll
    for (int m = 0; m < 4; m++)
        #pragma unroll
        for (int j = 0; j < 8; j++)
            #pragma unroll
            for (int q = 0; q < 4; q++) acc[m][j][q] = 0.f;

    const int aRow = lane & 15, aChunk = (lane >> 4) & 1;
    const int bRow = (lane & 7) | ((lane & 16) >> 1);
    const int bChunk = (lane >> 3) & 1;

    load_stage_d(sb, aBase, bBase, 0);
    CP_COMMIT();
    load_stage_d(sb + DSTG, aBase, bBase, 32);
    CP_COMMIT();

    const int NK = DF / 32;
    for (int it = 0; it < NK; it++) {
        CP_WAIT1();
        __syncthreads();

        const uint32_t Ab = sb + (it % 3) * DSTG;
        const uint32_t Bb = Ab + D_BH;
        #pragma unroll
        for (int ks = 0; ks < 2; ks++) {
            uint32_t ah[4][4], al[4][4], bh[4][4], bl[4][4];
            uint32_t aAddr = Ab + (warpM + aRow) * ROWB + ks * 32 + aChunk * 16;
            #pragma unroll
            for (int mt = 0; mt < 4; mt++) {
                LDSM4(ah[mt], aAddr + mt * 16 * ROWB);
                LDSM4(al[mt], aAddr + D_AL + mt * 16 * ROWB);
            }
            uint32_t bAddr = Bb + (warpN + bRow) * ROWB + ks * 32 + bChunk * 16;
            #pragma unroll
            for (int nt = 0; nt < 4; nt++) {
                LDSM4(bh[nt], bAddr + nt * 16 * ROWB);
                LDSM4(bl[nt], bAddr + (D_BL - D_BH) + nt * 16 * ROWB);
            }
            #pragma unroll
            for (int mt = 0; mt < 4; mt++)
                #pragma unroll
                for (int j = 0; j < 8; j++) {
                    const int nt = j >> 1, hf = (j & 1) * 2;
                    MMA16816(acc[mt][j], ah[mt], bh[nt][hf], bh[nt][hf + 1]);
                    MMA16816(acc[mt][j], ah[mt], bl[nt][hf], bl[nt][hf + 1]);
                    MMA16816(acc[mt][j], al[mt], bh[nt][hf], bh[nt][hf + 1]);
                }
        }

        if (it + 2 < NK) {
            load_stage_d(sb + ((it + 2) % 3) * DSTG, aBase, bBase, (it + 2) * 32);
            CP_COMMIT();
        }
    }

    // ---- epilogue ----
    __shared__ float sNi[256], sNj[128];
    sNi[tid] = g_fn[aBase + tid];
    if (tid < 128) sNj[tid] = g_fn[bBase + tid];
    __syncthreads();

    float* st = (float*)smem;   // [256][129]
    #pragma unroll
    for (int mt = 0; mt < 4; mt++) {
        const int r0 = warpM + mt * 16 + (lane >> 2);
        #pragma unroll
        for (int j = 0; j < 8; j++) {
            const int c0 = warpN + (j >> 1) * 16 + (j & 1) * 8 + 2 * (lane & 3);
            #pragma unroll
            for (int q = 0; q < 4; q++) {
                const int rr = r0 + (q >> 1) * 8;
                const int cc = c0 + (q & 1);
                st[rr * 129 + cc] = fmaxf(sNi[rr] + sNj[cc] - 2.f * acc[mt][j][q], 0.f);
            }
        }
    }
    __syncthreads();

    for (int x = tid; x < 256 * 128; x += 256) {
        int mm = x >> 7, cc = x & 127;
        g_D[(size_t)(aBase + mm) * N2 + (bBase + cc)] = st[mm * 129 + cc];
    }
    for (int x = tid; x < 128 * 256; x += 256) {
        int rc = x >> 8, cm = x & 255;
        int gi = aBase + cm, gj = bBase + rc;
        if (gj > gi) g_D[(size_t)gj * N2 + gi] = st[cm * 129 + rc];
    }
}

// ---------------------------------------------------------------------------
// LID: per row, exact radix-select of rank-32 / rank-512 squared distance
// ---------------------------------------------------------------------------
__global__ void __launch_bounds__(256) select_kernel(float* __restrict__ out)
{
    int r = blockIdx.x, tid = threadIdx.x;
    __shared__ unsigned skey[N2];
    __shared__ unsigned hist[256];
    __shared__ unsigned s_prefix;
    __shared__ int s_kk;
    __shared__ float sred[256];

    const float* drow = &g_D[(size_t)r * N2];
    for (int j = tid; j < N2; j += 256)
        skey[j] = (j == r) ? 0xFFFFFFFFu : __float_as_uint(drow[j]);
    __syncthreads();

    #pragma unroll
    for (int ksel = 0; ksel < 2; ksel++) {
        const int k = (ksel == 0) ? 32 : 512;
        if (tid == 0) { s_kk = k; s_prefix = 0u; }
        __syncthreads();
        unsigned prefix = 0u, pmask = 0u;

        for (int p = 3; p >= 0; p--) {
            hist[tid] = 0u;
            __syncthreads();
            const int sh = p * 8;
            for (int j = tid; j < N2; j += 256) {
                unsigned kv = skey[j];
                unsigned bin = 0xFFFFFFFFu;
                if ((kv & pmask) == prefix) bin = (kv >> sh) & 255u;
                unsigned mm = __match_any_sync(0xFFFFFFFFu, bin);
                if (bin != 0xFFFFFFFFu && (int)(__ffs(mm) - 1) == (int)(threadIdx.x & 31))
                    atomicAdd(&hist[bin], (unsigned)__popc(mm));
            }
            __syncthreads();
            if (tid == 0) {
                int kk = s_kk, cum = 0;
                for (int b2 = 0; b2 < 256; b2++) {
                    int c = (int)hist[b2];
                    if (cum + c >= kk) { s_prefix = prefix | ((unsigned)b2 << sh); s_kk = kk - cum; break; }
                    cum += c;
                }
            }
            __syncthreads();
            prefix = s_prefix;
            pmask |= (0xFFu << sh);
        }

        const unsigned Kk = prefix;
        const float lnK = 0.5f * logf(__uint_as_float(Kk));
        float s = 0.f;
        for (int j = tid; j < N2; j += 256) {
            unsigned kv = skey[j];
            if (kv < Kk) s += 0.5f * logf(__uint_as_float(kv)) - lnK;
        }
        sred[tid] = s; __syncthreads();
        for (int st = 128; st > 0; st >>= 1) { if (tid < st) sred[tid] += sred[tid + st]; __syncthreads(); }
        if (tid == 0)
            out[(ksel == 0 ? OUT_LIDS32 : OUT_LIDS512) + r] = -(float)k / sred[0];
        __syncthreads();
    }
}

// ---------------------------------------------------------------------------
extern "C" void kernel_launch(void* const* d_in, const int* in_sizes, int n_in,
                              void* d_out, int out_size)
{
    const float* z0 = (const float*)d_in[0];
    const float* z1 = (const float*)d_in[1];
    const float* f0 = (const float*)d_in[2];
    const float* f1 = (const float*)d_in[3];
    float* out = (float*)d_out;

    cudaFuncSetAttribute(dist_gemm_kernel,
                         cudaFuncAttributeMaxDynamicSharedMemorySize, DSMEM_DYN);
    cudaFuncSetAttribute(logits_gemm_kernel,
                         cudaFuncAttributeMaxDynamicSharedMemorySize, LSMEM_DYN);

    // order chosen so ncu's fixed capture slot (4th kernel) lands on dist_gemm
    prep_kernel<<<N2, 256>>>(z0, z1, f0, f1, out);
    logits_gemm_kernel<<<dim3(64, 64), 256, LSMEM_DYN>>>(out);
    loss_final_kernel<<<N2, 128>>>();
    dist_gemm_kernel<<<dim3(64, 32), 256, DSMEM_DYN>>>();
    finalize_kernel<<<1, 256>>>(out);
    select_kernel<<<N2, 256>>>(out);
}